// round 12
// baseline (speedup 1.0000x reference)
#include <cuda_runtime.h>
#include <math.h>
#include <stdint.h>

#define NV     12
#define BATCH  4096
#define DIM    128
#define ALPHA  0.4f
#define BETA   2.0f
#define LAMDA  2.0f

#define B_PER_BLK 4            // batch elements per block (1 warp each)
#define THREADS   128
#define NBLOCKS   (BATCH / B_PER_BLK)    // 1024
#define PITCH     68           // floats per smem row (64 data... 128 data + 8 pad)
// full row = 128 floats + 8 pad? No: PITCH=68 would be for 64. Full row needs
// 128 floats; pad to 132? -> we use PITCH=132? See below: rows hold 128 floats,
// pad +4 floats => 132. 132 % 32 = 4 -> same conflict-free pattern as PITCH=36.
#undef  PITCH
#define PITCH     132          // 128 data + 4 pad floats = 528 B row stride
#define ROWS      24           // 12 A rows + 12 N rows
#define WTILE     (ROWS * PITCH)         // 3168 floats per warp (12.7 KB)

// Per-block partials + ticket (device globals, zero-initialized)
__device__ float g_pl[NBLOCKS];
__device__ float g_pc[NBLOCKS];
__device__ float g_pm[NBLOCKS];
__device__ float g_pa[NBLOCKS];
__device__ float g_pmin[NBLOCKS];
__device__ unsigned int g_ticket;

__device__ __forceinline__ float dot4(float4 a, float4 b) {
    return a.x * b.x + a.y * b.y + a.z * b.z + a.w * b.w;
}
__device__ __forceinline__ float sqdiff4(float4 a, float4 b) {
    float x = a.x - b.x, y = a.y - b.y, z = a.z - b.z, w = a.w - b.w;
    return x * x + y * y + z * z + w * w;
}
__device__ __forceinline__ void cp_async16(uint32_t saddr, const void* gptr) {
    asm volatile("cp.async.cg.shared.global [%0], [%1], 16;"
                 :: "r"(saddr), "l"(gptr));
}
#define CP_COMMIT()  asm volatile("cp.async.commit_group;")
#define CP_WAIT0()   asm volatile("cp.async.wait_group 0;")

// order-preserving float -> u32 key (works for negatives too)
__device__ __forceinline__ unsigned fkey(float x) {
    unsigned b = __float_as_uint(x);
    return b ^ ((b & 0x80000000u) ? 0xFFFFFFFFu : 0x80000000u);
}
__device__ __forceinline__ float fkey_inv(unsigned k) {
    unsigned b = (k & 0x80000000u) ? (k ^ 0x80000000u) : ~k;
    return __uint_as_float(b);
}

__global__ __launch_bounds__(THREADS, 7)
void pil_fused(const float* __restrict__ SV_A, const float* __restrict__ SV_N,
               const float* __restrict__ MV_A, const float* __restrict__ MV_N,
               float* __restrict__ out, int out_size)
{
    // 4 warps x 3168 floats = 50.7 KB?  No: WTILE = 24*132 = 3168 floats
    // = 12672 B per warp; x4 warps = 50688 B.  That exceeds 48K static limit?
    // Static smem limit is 48KB... use dynamic? Keep it simple: static arrays
    // up to 48KB are allowed; 50.7KB is NOT. Solution: PITCH=132 only for the
    // data region we index; shrink pad: use PITCH=132 but share the last
    // row's pad... Instead reduce to 4 warps x 24 x 130? 130%4!=0. Use
    // dynamic shared memory with cudaFuncSetAttribute (allowed: attribute
    // setting is not allocation).
    extern __shared__ float tile[];             // 4 * WTILE floats
    __shared__ float nrm[B_PER_BLK * ROWS];     // 96 row norms
    __shared__ float r_loss[B_PER_BLK], r_cnt[B_PER_BLK];
    __shared__ float r_mc[B_PER_BLK], r_ac[B_PER_BLK], r_mn[B_PER_BLK];
    __shared__ float red[5][THREADS];
    __shared__ int   s_islast;

    const int tid  = threadIdx.x;
    const int lane = tid & 31;
    const int w    = tid >> 5;       // warp = local batch element 0..3
    const int h    = lane >> 4;      // dim-half: dims [h*64, h*64+64)
    const int t    = lane & 15;
    const int ti   = t >> 2;         // A rows 3*ti..3*ti+2
    const int tj   = t & 3;          // N rows 3*tj..3*tj+2
    const int bg   = blockIdx.x * B_PER_BLK + w;

    float* wbuf = &tile[w * WTILE];
    const uint32_t wbase = (uint32_t)__cvta_generic_to_shared(wbuf);

    // ---- single-shot full-tile staging: 24 rows x 512 B, one cp.async per
    //      row per lane (lane = k4 index 0..31). 24 cp in flight per lane
    //      stream -> per warp 12.3 KB outstanding before the single wait.
    {
        const float* baseA = SV_A + (size_t)bg * DIM + lane * 4;
        const float* baseN = SV_N + (size_t)bg * DIM + lane * 4;
        const size_t  VS   = (size_t)BATCH * DIM;     // view-row stride
        #pragma unroll
        for (int s = 0; s < NV; ++s)
            cp_async16(wbase + (uint32_t)(s * PITCH * 4) + lane * 16,
                       baseA + s * VS);
        #pragma unroll
        for (int s = 0; s < NV; ++s)
            cp_async16(wbase + (uint32_t)((NV + s) * PITCH * 4) + lane * 16,
                       baseN + s * VS);
        CP_COMMIT();
    }

    float G[3][3] = {{0.f,0.f,0.f},{0.f,0.f,0.f},{0.f,0.f,0.f}};

    CP_WAIT0();
    __syncwarp();

    // ---- norm pass: lanes 0..23 own one full 128-dim row; 4 accumulators
    //      to break the FFMA dependency chain
    float nacc = 0.f;
    if (lane < ROWS) {
        const float* rb = wbuf + lane * PITCH;
        float s0 = 0.f, s1 = 0.f, s2 = 0.f, s3 = 0.f;
        #pragma unroll
        for (int k4 = 0; k4 < 32; k4 += 4) {
            float4 v0 = *reinterpret_cast<const float4*>(rb + (k4 + 0) * 4);
            float4 v1 = *reinterpret_cast<const float4*>(rb + (k4 + 1) * 4);
            float4 v2 = *reinterpret_cast<const float4*>(rb + (k4 + 2) * 4);
            float4 v3 = *reinterpret_cast<const float4*>(rb + (k4 + 3) * 4);
            s0 += dot4(v0, v0); s1 += dot4(v1, v1);
            s2 += dot4(v2, v2); s3 += dot4(v3, v3);
        }
        nacc = (s0 + s1) + (s2 + s3);
    }

    // ---- 3x3 register-tiled Gram over this lane's 64-dim half
    {
        const float* A0 = wbuf + (3 * ti)      * PITCH + h * 64;
        const float* N0 = wbuf + (NV + 3 * tj) * PITCH + h * 64;
        #pragma unroll
        for (int k4 = 0; k4 < 16; ++k4) {
            float4 a0 = *reinterpret_cast<const float4*>(A0 + 0 * PITCH + k4 * 4);
            float4 a1 = *reinterpret_cast<const float4*>(A0 + 1 * PITCH + k4 * 4);
            float4 a2 = *reinterpret_cast<const float4*>(A0 + 2 * PITCH + k4 * 4);
            float4 n0 = *reinterpret_cast<const float4*>(N0 + 0 * PITCH + k4 * 4);
            float4 n1 = *reinterpret_cast<const float4*>(N0 + 1 * PITCH + k4 * 4);
            float4 n2 = *reinterpret_cast<const float4*>(N0 + 2 * PITCH + k4 * 4);
            G[0][0] += dot4(a0, n0); G[0][1] += dot4(a0, n1); G[0][2] += dot4(a0, n2);
            G[1][0] += dot4(a1, n0); G[1][1] += dot4(a1, n1); G[1][2] += dot4(a1, n2);
            G[2][0] += dot4(a2, n0); G[2][1] += dot4(a2, n1); G[2][2] += dot4(a2, n2);
        }
    }

    // ---- hoist argmin-independent epilogue loads (overlap the tail)
    float4 ma  = reinterpret_cast<const float4*>(MV_A + (size_t)bg * DIM)[lane];
    float4 mn_ = reinterpret_cast<const float4*>(MV_N + (size_t)bg * DIM)[lane];

    // publish full-dim norms (warp-local region)
    if (lane < ROWS) nrm[w * ROWS + lane] = nacc;

    // ---- combine 64-dim halves of G (offset-16 butterfly)
    #pragma unroll
    for (int r = 0; r < 3; ++r)
        #pragma unroll
        for (int cc = 0; cc < 3; ++cc)
            G[r][cc] += __shfl_xor_sync(0xffffffffu, G[r][cc], 16);
    __syncwarp();                  // nrm visible within warp

    // ---- d = na + nn - 2G, local argmin with flat-index tie-break
    float dmin = 3.4e38f;
    int   imin = 0;
    #pragma unroll
    for (int r = 0; r < 3; ++r) {
        float na = nrm[w * ROWS + 3 * ti + r];
        #pragma unroll
        for (int cc = 0; cc < 3; ++cc) {
            float nn = nrm[w * ROWS + NV + 3 * tj + cc];
            float d  = na + nn - 2.f * G[r][cc];
            int   fl = (3 * ti + r) * NV + (3 * tj + cc);
            if (d < dmin || (d == dmin && fl < imin)) { dmin = d; imin = fl; }
        }
    }
    // ---- warp argmin via 2 REDUX ops (replaces 8 dependent shuffles)
    unsigned mykey = fkey(dmin);
    unsigned gkey  = __reduce_min_sync(0xffffffffu, mykey);
    unsigned cand  = (mykey == gkey) ? (unsigned)imin : 0xFFFFFFFFu;
    imin = (int)__reduce_min_sync(0xffffffffu, cand);
    dmin = fkey_inv(gkey);

    // ---- dependent conf-row loads: 1 float4 per lane per array
    const int confA = imin / NV;
    const int confN = imin - confA * NV;

    float4 fa = reinterpret_cast<const float4*>(SV_A + ((size_t)confA * BATCH + bg) * DIM)[lane];
    float4 fn = reinterpret_cast<const float4*>(SV_N + ((size_t)confN * BATCH + bg) * DIM)[lane];

    float smv = sqdiff4(ma, mn_);
    float sa  = sqdiff4(ma, fa);
    float sc  = sqdiff4(mn_, fn);
    #pragma unroll
    for (int o = 1; o < 32; o <<= 1) {
        smv += __shfl_xor_sync(0xffffffffu, smv, o);
        sa  += __shfl_xor_sync(0xffffffffu, sa,  o);
        sc  += __shfl_xor_sync(0xffffffffu, sc,  o);
    }

    if (lane == 0) {
        float mc       = fmaxf(dmin, 0.f);
        float mv_inter = sqrtf(smv);
        float a_cl     = sqrtf(sa);
        float c_in     = sqrtf(sc);
        float loss = LAMDA * (fmaxf(BETA - mc, 0.f) + fmaxf(BETA - mv_inter, 0.f))
                   + fmaxf(a_cl - ALPHA, 0.f) + fmaxf(c_in - ALPHA, 0.f);
        float sqmc = sqrtf(mc);
        r_loss[w] = loss;
        r_cnt[w]  = (loss != 0.f) ? 1.f : 0.f;
        r_mc[w]   = sqmc;
        r_ac[w]   = sqrtf(a_cl) + sqrtf(c_in);
        r_mn[w]   = sqmc;
    }
    __syncthreads();

    // ---- per-block partial (fixed order -> deterministic) + ticket
    if (tid == 0) {
        float sl = 0.f, sn = 0.f, sm = 0.f, sa2 = 0.f, mn = 3.4e38f;
        #pragma unroll
        for (int i = 0; i < B_PER_BLK; ++i) {
            sl  += r_loss[i];
            sn  += r_cnt[i];
            sm  += r_mc[i];
            sa2 += r_ac[i];
            mn   = fminf(mn, r_mn[i]);
        }
        g_pl[blockIdx.x]   = sl;
        g_pc[blockIdx.x]   = sn;
        g_pm[blockIdx.x]   = sm;
        g_pa[blockIdx.x]   = sa2;
        g_pmin[blockIdx.x] = mn;
        __threadfence();
        unsigned int prev = atomicAdd(&g_ticket, 1u);
        s_islast = (prev == NBLOCKS - 1) ? 1 : 0;
    }
    __syncthreads();

    // ---- last block: deterministic final reduction over 1024 partials
    if (s_islast) {
        __threadfence();
        float al = 0.f, ac = 0.f, am = 0.f, aa = 0.f, amn = 3.4e38f;
        #pragma unroll
        for (int q = 0; q < NBLOCKS / THREADS; ++q) {   // 8, fixed order
            int i = tid + q * THREADS;
            al += g_pl[i];
            ac += g_pc[i];
            am += g_pm[i];
            aa += g_pa[i];
            amn = fminf(amn, g_pmin[i]);
        }
        red[0][tid] = al; red[1][tid] = ac; red[2][tid] = am;
        red[3][tid] = aa; red[4][tid] = amn;
        __syncthreads();
        for (int o = THREADS / 2; o > 0; o >>= 1) {
            if (tid < o) {
                red[0][tid] += red[0][tid + o];
                red[1][tid] += red[1][tid + o];
                red[2][tid] += red[2][tid + o];
                red[3][tid] += red[3][tid + o];
                red[4][tid]  = fminf(red[4][tid], red[4][tid + o]);
            }
            __syncthreads();
        }
        if (tid == 0) {
            const float inv = 1.f / (float)BATCH;
            if (out_size > 0) out[0] = red[0][0] * inv;          // avg_loss
            if (out_size > 1) out[1] = red[1][0];                // count_nonzero
            if (out_size > 2) out[2] = red[2][0] * inv;          // mean(sqrt(mc))
            if (out_size > 3) out[3] = 0.5f * red[3][0] * inv;   // cluster means
            if (out_size > 4) out[4] = red[4][0];                // min(sqrt(mc))
            for (int i = 5; i < out_size; ++i) out[i] = 0.f;
            g_ticket = 0;      // reset for next graph replay
        }
    }
}

extern "C" void kernel_launch(void* const* d_in, const int* in_sizes, int n_in,
                              void* d_out, int out_size)
{
    const float* SV_A = (const float*)d_in[0];
    const float* SV_N = (const float*)d_in[1];
    const float* MV_A = (const float*)d_in[2];
    const float* MV_N = (const float*)d_in[3];
    (void)in_sizes; (void)n_in;

    const int smem_bytes = 4 * WTILE * sizeof(float);   // 50688 B
    cudaFuncSetAttribute(pil_fused, cudaFuncAttributeMaxDynamicSharedMemorySize,
                         smem_bytes);
    pil_fused<<<NBLOCKS, THREADS, smem_bytes>>>(SV_A, SV_N, MV_A, MV_N,
                                                (float*)d_out, out_size);
}